// round 2
// baseline (speedup 1.0000x reference)
#include <cuda_runtime.h>
#include <math.h>
#include <stdint.h>

// Problem constants
#define BSZ 4
#define NSEQ 2048
#define DMODEL 256
#define HH 8
#define DHD 32
#define RR 64
#define KSP 32
#define MROWS (BSZ * NSEQ)   // 8192

// ---------------------------------------------------------------------------
// Single scratch arena (float offsets). No cudaGetSymbolAddress needed:
// kernels reference g_arena directly with compile-time offsets.
// ---------------------------------------------------------------------------
#define OFF_T   ((size_t)0)                                   // 8192*64
#define OFF_H   (OFF_T  + (size_t)MROWS * RR)
#define OFF_Q   (OFF_H  + (size_t)MROWS * DMODEL)
#define OFF_K   (OFF_Q  + (size_t)MROWS * DMODEL)
#define OFF_V   (OFF_K  + (size_t)MROWS * DMODEL)
#define OFF_O   (OFF_V  + (size_t)MROWS * DMODEL)
#define OFF_O2  (OFF_O  + (size_t)MROWS * DMODEL)
#define OFF_SC  (OFF_O2 + (size_t)MROWS * DMODEL)             // 512 MB scores
#define OFF_PS  (OFF_SC + (size_t)BSZ * HH * NSEQ * NSEQ)
#define OFF_PQ  (OFF_PS + (size_t)64 * DMODEL)
#define OFF_ST  (OFF_PQ + (size_t)64 * DMODEL)
#define ARENA_TOTAL (OFF_ST + (size_t)2 * DMODEL)

__device__ float g_arena[ARENA_TOTAL];

// ---------------------------------------------------------------------------
// Generic tiled SGEMM: C[M,N] = A[M,K] @ B[K,N] (+ bias[N])
// A is either external (Aext != nullptr) or arena + aOff. C is arena + cOff.
// BM=BN=64, BK=16, 256 threads, 4x4 per thread. M,N,K multiples of tiles.
// ---------------------------------------------------------------------------
__global__ void sgemm_kernel(const float* __restrict__ Aext, size_t aOff,
                             const float* __restrict__ Bm,
                             const float* __restrict__ bias,
                             size_t cOff,
                             int M, int Nn, int K) {
    const float* A = Aext ? Aext : (g_arena + aOff);
    float* C = g_arena + cOff;
    __shared__ float As[16][65];   // [k][m]
    __shared__ float Bs[16][65];   // [k][n]
    int tid = threadIdx.x;
    int tx = tid & 15, ty = tid >> 4;
    int m0 = blockIdx.y * 64, n0 = blockIdx.x * 64;
    float acc[4][4] = {};

    for (int k0 = 0; k0 < K; k0 += 16) {
#pragma unroll
        for (int r = 0; r < 4; r++) {
            int idx = tid + r * 256;
            int m = idx >> 4;          // 0..63
            int kk = idx & 15;
            As[kk][m] = A[(size_t)(m0 + m) * K + k0 + kk];
        }
#pragma unroll
        for (int r = 0; r < 4; r++) {
            int idx = tid + r * 256;
            int kk = idx >> 6;         // 0..15
            int nn = idx & 63;
            Bs[kk][nn] = Bm[(size_t)(k0 + kk) * Nn + n0 + nn];
        }
        __syncthreads();
#pragma unroll
        for (int kk = 0; kk < 16; kk++) {
            float a4[4], b4[4];
#pragma unroll
            for (int i = 0; i < 4; i++) a4[i] = As[kk][ty * 4 + i];
#pragma unroll
            for (int j = 0; j < 4; j++) b4[j] = Bs[kk][tx * 4 + j];
#pragma unroll
            for (int i = 0; i < 4; i++)
#pragma unroll
                for (int j = 0; j < 4; j++)
                    acc[i][j] += a4[i] * b4[j];
        }
        __syncthreads();
    }
#pragma unroll
    for (int i = 0; i < 4; i++) {
        int m = m0 + ty * 4 + i;
#pragma unroll
        for (int j = 0; j < 4; j++) {
            int n = n0 + tx * 4 + j;
            float v = acc[i][j];
            if (bias) v += bias[n];
            C[(size_t)m * Nn + n] = v;
        }
    }
}

// ---------------------------------------------------------------------------
// QK^T scores per (b,h): S[bh][i][j] = (q_i . k_j) / sqrt(32)
// grid (N/64 j-tiles, N/64 i-tiles, B*H), 256 threads, 64x64 tile, K=32.
// q,k in arena, stored [B,N,D]; head h occupies cols [h*32, h*32+32).
// ---------------------------------------------------------------------------
__global__ void qk_kernel() {
    const float* q = g_arena + OFF_Q;
    const float* k = g_arena + OFF_K;
    float* S = g_arena + OFF_SC;
    int bh = blockIdx.z;
    int h = bh & (HH - 1), b = bh >> 3;
    int i0 = blockIdx.y * 64, j0 = blockIdx.x * 64;
    __shared__ float Qs[64][33];
    __shared__ float Ks[64][33];
    int tid = threadIdx.x;
    int d = tid & 31, r0 = tid >> 5;
    const float* qb = q + ((size_t)b * NSEQ) * DMODEL + h * DHD;
    const float* kb = k + ((size_t)b * NSEQ) * DMODEL + h * DHD;
#pragma unroll
    for (int r = r0; r < 64; r += 8) {
        Qs[r][d] = qb[(size_t)(i0 + r) * DMODEL + d];
        Ks[r][d] = kb[(size_t)(j0 + r) * DMODEL + d];
    }
    __syncthreads();
    int tx = tid & 15, ty = tid >> 4;
    float acc[4][4] = {};
#pragma unroll
    for (int dd = 0; dd < 32; dd++) {
        float a4[4], b4[4];
#pragma unroll
        for (int i = 0; i < 4; i++) a4[i] = Qs[ty * 4 + i][dd];
#pragma unroll
        for (int j = 0; j < 4; j++) b4[j] = Ks[tx * 4 + j][dd];
#pragma unroll
        for (int i = 0; i < 4; i++)
#pragma unroll
            for (int j = 0; j < 4; j++)
                acc[i][j] += a4[i] * b4[j];
    }
    const float scale = 1.0f / sqrtf(32.0f);
    float* Sp = S + ((size_t)bh * NSEQ + i0) * NSEQ + j0;
#pragma unroll
    for (int i = 0; i < 4; i++)
#pragma unroll
        for (int j = 0; j < 4; j++)
            Sp[(size_t)(ty * 4 + i) * NSEQ + tx * 4 + j] = acc[i][j] * scale;
}

// ---------------------------------------------------------------------------
// Fused per-row: exact top-32 threshold (radix select), masked softmax, P @ V.
// One block (256 threads) per (b,h,query row). grid = B*H*N = 65536.
// ---------------------------------------------------------------------------
__device__ __forceinline__ unsigned fkey(float f) {
    unsigned u = __float_as_uint(f);
    return u ^ (((int)u < 0) ? 0xFFFFFFFFu : 0x80000000u);
}

__device__ __forceinline__ float blkReduceMax(float v, float* red) {
#pragma unroll
    for (int o = 16; o; o >>= 1) v = fmaxf(v, __shfl_xor_sync(0xffffffffu, v, o));
    if ((threadIdx.x & 31) == 0) red[threadIdx.x >> 5] = v;
    __syncthreads();
    if (threadIdx.x == 0) {
        float m = red[0];
#pragma unroll
        for (int i = 1; i < 8; i++) m = fmaxf(m, red[i]);
        red[0] = m;
    }
    __syncthreads();
    float r = red[0];
    __syncthreads();
    return r;
}

__device__ __forceinline__ float blkReduceSum(float v, float* red) {
#pragma unroll
    for (int o = 16; o; o >>= 1) v += __shfl_xor_sync(0xffffffffu, v, o);
    if ((threadIdx.x & 31) == 0) red[threadIdx.x >> 5] = v;
    __syncthreads();
    if (threadIdx.x == 0) {
        float m = red[0];
#pragma unroll
        for (int i = 1; i < 8; i++) m += red[i];
        red[0] = m;
    }
    __syncthreads();
    float r = red[0];
    __syncthreads();
    return r;
}

__global__ void attn_row_kernel() {
    const float* S = g_arena + OFF_SC;
    const float* v = g_arena + OFF_V;
    float* o = g_arena + OFF_O;

    __shared__ float s[NSEQ];
    __shared__ unsigned hist[256];
    __shared__ float red[8];
    __shared__ float part[256];
    __shared__ unsigned sh_pref, sh_k;

    int row = blockIdx.x;
    int n = row & (NSEQ - 1);
    int bh = row >> 11;
    int h = bh & (HH - 1), b = bh >> 3;
    int t = threadIdx.x;

    const float* srow = S + ((size_t)bh * NSEQ + n) * NSEQ;
    for (int i = t; i < NSEQ; i += 256) s[i] = srow[i];
    if (t == 0) { sh_pref = 0u; sh_k = KSP; }
    __syncthreads();

    // Radix select: exact 32nd-largest key (counting duplicates, so the
    // >= threshold semantics match jax.lax.top_k's k-th sorted value).
    for (int shift = 24; shift >= 0; shift -= 8) {
        hist[t] = 0u;
        __syncthreads();
        unsigned pref = sh_pref;
        unsigned kneed = sh_k;
        unsigned mask = (shift == 24) ? 0u : (0xFFFFFFFFu << (shift + 8));
        for (int i = t; i < NSEQ; i += 256) {
            unsigned key = fkey(s[i]);
            if ((key & mask) == pref) atomicAdd(&hist[(key >> shift) & 255u], 1u);
        }
        __syncthreads();
        // inclusive suffix sums over 256 buckets (Hillis-Steele)
        for (int off = 1; off < 256; off <<= 1) {
            unsigned add = (t + off < 256) ? hist[t + off] : 0u;
            __syncthreads();
            hist[t] += add;
            __syncthreads();
        }
        unsigned suf = hist[t];
        unsigned sufN = (t < 255) ? hist[t + 1] : 0u;
        if (suf >= kneed && sufN < kneed) {
            sh_pref = pref | ((unsigned)t << shift);
            sh_k = kneed - sufN;
        }
        __syncthreads();
    }
    unsigned thr = sh_pref;

    // row max (the max element is always kept, so max over all == max over kept)
    float m = -INFINITY;
    for (int i = t; i < NSEQ; i += 256) m = fmaxf(m, s[i]);
    m = blkReduceMax(m, red);

    // masked exp, store probs in place, accumulate sum
    float loc = 0.f;
    for (int i = t; i < NSEQ; i += 256) {
        float sv = s[i];
        float p = (fkey(sv) >= thr) ? expf(sv - m) : 0.f;
        s[i] = p;
        loc += p;
    }
    float tot = blkReduceSum(loc, red);   // syncs also publish s[] writes
    float inv = 1.f / tot;

    // P @ V: warp w handles j ≡ w (mod 8); lane d reads V[j][h*32+d] (coalesced)
    int w = t >> 5, d = t & 31;
    const float* vb = v + ((size_t)b * NSEQ) * DMODEL + h * DHD + d;
    float acc = 0.f;
#pragma unroll 4
    for (int j = w; j < NSEQ; j += 8)
        acc += s[j] * vb[(size_t)j * DMODEL];
    part[t] = acc;
    __syncthreads();
    if (t < 32) {
        float r = part[t];
#pragma unroll
        for (int ww = 1; ww < 8; ww++) r += part[ww * 32 + t];
        o[((size_t)b * NSEQ + n) * DMODEL + h * DHD + t] = r * inv;
    }
}

// ---------------------------------------------------------------------------
// BatchNorm over (B,N) per channel — deterministic two-stage reduction.
// Input (pre-BN activations) lives at OFF_H (reused).
// ---------------------------------------------------------------------------
__global__ void bn_partial_kernel() {
    const float* X = g_arena + OFF_H;
    float* ps = g_arena + OFF_PS;
    float* pq = g_arena + OFF_PQ;
    int blk = blockIdx.x;           // 64 blocks x 128 rows
    int t = threadIdx.x;            // channel
    float s = 0.f, q = 0.f;
    for (int r = 0; r < 128; r++) {
        float val = X[(size_t)(blk * 128 + r) * DMODEL + t];
        s += val;
        q += val * val;
    }
    ps[blk * DMODEL + t] = s;
    pq[blk * DMODEL + t] = q;
}

__global__ void bn_finalize_kernel() {
    const float* ps = g_arena + OFF_PS;
    const float* pq = g_arena + OFF_PQ;
    float* stat = g_arena + OFF_ST;
    int t = threadIdx.x;
    float s = 0.f, q = 0.f;
    for (int b = 0; b < 64; b++) {
        s += ps[b * DMODEL + t];
        q += pq[b * DMODEL + t];
    }
    float mu = s * (1.0f / (float)MROWS);
    float var = q * (1.0f / (float)MROWS) - mu * mu;
    stat[t] = mu;
    stat[DMODEL + t] = rsqrtf(var + 1e-5f);
}

__global__ void bn_apply_kernel(const float* __restrict__ gamma,
                                const float* __restrict__ beta,
                                float* __restrict__ out) {
    const float* X = g_arena + OFF_H;
    const float* stat = g_arena + OFF_ST;
    size_t idx = (size_t)blockIdx.x * 256 + threadIdx.x;
    int c = (int)(idx & (DMODEL - 1));
    out[idx] = (X[idx] - stat[c]) * stat[DMODEL + c] * gamma[c] + beta[c];
}

// ---------------------------------------------------------------------------
// Launch — kernel launches ONLY (graph-capture safe, no runtime API calls)
// ---------------------------------------------------------------------------
extern "C" void kernel_launch(void* const* d_in, const int* in_sizes, int n_in,
                              void* d_out, int out_size) {
    const float* x    = (const float*)d_in[0];
    const float* U_np = (const float*)d_in[1];
    const float* V_np = (const float*)d_in[2];
    const float* b_np = (const float*)d_in[3];
    const float* U_q  = (const float*)d_in[4];
    const float* V_q  = (const float*)d_in[5];
    const float* U_k  = (const float*)d_in[6];
    const float* V_k  = (const float*)d_in[7];
    const float* U_v  = (const float*)d_in[8];
    const float* V_v  = (const float*)d_in[9];
    const float* U_o  = (const float*)d_in[10];
    const float* V_o  = (const float*)d_in[11];
    const float* b_o  = (const float*)d_in[12];
    const float* U_op = (const float*)d_in[13];
    const float* V_op = (const float*)d_in[14];
    const float* b_op = (const float*)d_in[15];
    const float* gamma = (const float*)d_in[16];
    const float* beta  = (const float*)d_in[17];
    float* out = (float*)d_out;

    dim3 gN1(1, MROWS / 64);   // Nn = 64
    dim3 gN4(4, MROWS / 64);   // Nn = 256

    // h = (x @ U_np) @ V_np + b_np
    sgemm_kernel<<<gN1, 256>>>(x, 0, U_np, nullptr, OFF_T, MROWS, RR, DMODEL);
    sgemm_kernel<<<gN4, 256>>>(nullptr, OFF_T, V_np, b_np, OFF_H, MROWS, DMODEL, RR);
    // q, k, v
    sgemm_kernel<<<gN1, 256>>>(nullptr, OFF_H, U_q, nullptr, OFF_T, MROWS, RR, DMODEL);
    sgemm_kernel<<<gN4, 256>>>(nullptr, OFF_T, V_q, nullptr, OFF_Q, MROWS, DMODEL, RR);
    sgemm_kernel<<<gN1, 256>>>(nullptr, OFF_H, U_k, nullptr, OFF_T, MROWS, RR, DMODEL);
    sgemm_kernel<<<gN4, 256>>>(nullptr, OFF_T, V_k, nullptr, OFF_K, MROWS, DMODEL, RR);
    sgemm_kernel<<<gN1, 256>>>(nullptr, OFF_H, U_v, nullptr, OFF_T, MROWS, RR, DMODEL);
    sgemm_kernel<<<gN4, 256>>>(nullptr, OFF_T, V_v, nullptr, OFF_V, MROWS, DMODEL, RR);

    // scores
    qk_kernel<<<dim3(NSEQ / 64, NSEQ / 64, BSZ * HH), 256>>>();
    // top-k + softmax + PV
    attn_row_kernel<<<BSZ * HH * NSEQ, 256>>>();

    // attention out proj + out_proj
    sgemm_kernel<<<gN1, 256>>>(nullptr, OFF_O, U_o, nullptr, OFF_T, MROWS, RR, DMODEL);
    sgemm_kernel<<<gN4, 256>>>(nullptr, OFF_T, V_o, b_o, OFF_O2, MROWS, DMODEL, RR);
    sgemm_kernel<<<gN1, 256>>>(nullptr, OFF_O2, U_op, nullptr, OFF_T, MROWS, RR, DMODEL);
    sgemm_kernel<<<gN4, 256>>>(nullptr, OFF_T, V_op, b_op, OFF_H, MROWS, DMODEL, RR);

    // BatchNorm
    bn_partial_kernel<<<64, 256>>>();
    bn_finalize_kernel<<<1, 256>>>();
    bn_apply_kernel<<<(MROWS * DMODEL) / 256, 256>>>(gamma, beta, out);
}

// round 3
// speedup vs baseline: 2.1557x; 2.1557x over previous
#include <cuda_runtime.h>
#include <math.h>
#include <stdint.h>

// Problem constants
#define BSZ 4
#define NSEQ 2048
#define DMODEL 256
#define HH 8
#define DHD 32
#define RR 64
#define KSP 32
#define MROWS (BSZ * NSEQ)   // 8192

// ---------------------------------------------------------------------------
// Single scratch arena (float offsets), compile-time indexed.
// ---------------------------------------------------------------------------
#define OFF_T   ((size_t)0)
#define OFF_H   (OFF_T  + (size_t)MROWS * RR)
#define OFF_Q   (OFF_H  + (size_t)MROWS * DMODEL)
#define OFF_K   (OFF_Q  + (size_t)MROWS * DMODEL)
#define OFF_V   (OFF_K  + (size_t)MROWS * DMODEL)
#define OFF_O   (OFF_V  + (size_t)MROWS * DMODEL)
#define OFF_O2  (OFF_O  + (size_t)MROWS * DMODEL)
#define OFF_SC  (OFF_O2 + (size_t)MROWS * DMODEL)             // 512 MB scores
#define OFF_PS  (OFF_SC + (size_t)BSZ * HH * NSEQ * NSEQ)
#define OFF_PQ  (OFF_PS + (size_t)64 * DMODEL)
#define OFF_ST  (OFF_PQ + (size_t)64 * DMODEL)
#define ARENA_TOTAL (OFF_ST + (size_t)2 * DMODEL)

__device__ float g_arena[ARENA_TOTAL];

// ---------------------------------------------------------------------------
// Generic tiled SGEMM: C[M,N] = A[M,K] @ B[K,N] (+ bias[N])
// ---------------------------------------------------------------------------
__global__ void sgemm_kernel(const float* __restrict__ Aext, size_t aOff,
                             const float* __restrict__ Bm,
                             const float* __restrict__ bias,
                             size_t cOff,
                             int M, int Nn, int K) {
    const float* A = Aext ? Aext : (g_arena + aOff);
    float* C = g_arena + cOff;
    __shared__ float As[16][65];   // [k][m]
    __shared__ float Bs[16][65];   // [k][n]
    int tid = threadIdx.x;
    int tx = tid & 15, ty = tid >> 4;
    int m0 = blockIdx.y * 64, n0 = blockIdx.x * 64;
    float acc[4][4] = {};

    for (int k0 = 0; k0 < K; k0 += 16) {
#pragma unroll
        for (int r = 0; r < 4; r++) {
            int idx = tid + r * 256;
            int m = idx >> 4;
            int kk = idx & 15;
            As[kk][m] = A[(size_t)(m0 + m) * K + k0 + kk];
        }
#pragma unroll
        for (int r = 0; r < 4; r++) {
            int idx = tid + r * 256;
            int kk = idx >> 6;
            int nn = idx & 63;
            Bs[kk][nn] = Bm[(size_t)(k0 + kk) * Nn + n0 + nn];
        }
        __syncthreads();
#pragma unroll
        for (int kk = 0; kk < 16; kk++) {
            float a4[4], b4[4];
#pragma unroll
            for (int i = 0; i < 4; i++) a4[i] = As[kk][ty * 4 + i];
#pragma unroll
            for (int j = 0; j < 4; j++) b4[j] = Bs[kk][tx * 4 + j];
#pragma unroll
            for (int i = 0; i < 4; i++)
#pragma unroll
                for (int j = 0; j < 4; j++)
                    acc[i][j] += a4[i] * b4[j];
        }
        __syncthreads();
    }
#pragma unroll
    for (int i = 0; i < 4; i++) {
        int m = m0 + ty * 4 + i;
#pragma unroll
        for (int j = 0; j < 4; j++) {
            int n = n0 + tx * 4 + j;
            float v = acc[i][j];
            if (bias) v += bias[n];
            C[(size_t)m * Nn + n] = v;
        }
    }
}

// ---------------------------------------------------------------------------
// QK^T scores per (b,h): S[bh][i][j] = (q_i . k_j) / sqrt(32)
// float4 stores (each thread owns 4 consecutive j).
// ---------------------------------------------------------------------------
__global__ void qk_kernel() {
    const float* q = g_arena + OFF_Q;
    const float* k = g_arena + OFF_K;
    float* S = g_arena + OFF_SC;
    int bh = blockIdx.z;
    int h = bh & (HH - 1), b = bh >> 3;
    int i0 = blockIdx.y * 64, j0 = blockIdx.x * 64;
    __shared__ float Qs[64][33];
    __shared__ float Ks[64][33];
    int tid = threadIdx.x;
    int d = tid & 31, r0 = tid >> 5;
    const float* qb = q + ((size_t)b * NSEQ) * DMODEL + h * DHD;
    const float* kb = k + ((size_t)b * NSEQ) * DMODEL + h * DHD;
#pragma unroll
    for (int r = r0; r < 64; r += 8) {
        Qs[r][d] = qb[(size_t)(i0 + r) * DMODEL + d];
        Ks[r][d] = kb[(size_t)(j0 + r) * DMODEL + d];
    }
    __syncthreads();
    int tx = tid & 15, ty = tid >> 4;
    float acc[4][4] = {};
#pragma unroll
    for (int dd = 0; dd < 32; dd++) {
        float a4[4], b4[4];
#pragma unroll
        for (int i = 0; i < 4; i++) a4[i] = Qs[ty * 4 + i][dd];
#pragma unroll
        for (int j = 0; j < 4; j++) b4[j] = Ks[tx * 4 + j][dd];
#pragma unroll
        for (int i = 0; i < 4; i++)
#pragma unroll
            for (int j = 0; j < 4; j++)
                acc[i][j] += a4[i] * b4[j];
    }
    const float scale = 1.0f / sqrtf(32.0f);
    float* Sp = S + ((size_t)bh * NSEQ + i0) * NSEQ + j0;
#pragma unroll
    for (int i = 0; i < 4; i++) {
        float4 v4 = make_float4(acc[i][0] * scale, acc[i][1] * scale,
                                acc[i][2] * scale, acc[i][3] * scale);
        *reinterpret_cast<float4*>(Sp + (size_t)(ty * 4 + i) * NSEQ + tx * 4) = v4;
    }
}

// ---------------------------------------------------------------------------
// Fused per-row: exact top-32 threshold (radix select on register-resident
// keys), deterministic compaction, sparse exp + sparse P @ V.
// One block (256 threads) per (b,h,row). grid = B*H*N = 65536.
// ---------------------------------------------------------------------------
__device__ __forceinline__ unsigned fkey(float f) {
    unsigned u = __float_as_uint(f);
    return u ^ (((int)u < 0) ? 0xFFFFFFFFu : 0x80000000u);
}

__device__ __forceinline__ float blkReduceMax(float v, float* red) {
#pragma unroll
    for (int o = 16; o; o >>= 1) v = fmaxf(v, __shfl_xor_sync(0xffffffffu, v, o));
    if ((threadIdx.x & 31) == 0) red[threadIdx.x >> 5] = v;
    __syncthreads();
    if (threadIdx.x == 0) {
        float m = red[0];
#pragma unroll
        for (int i = 1; i < 8; i++) m = fmaxf(m, red[i]);
        red[0] = m;
    }
    __syncthreads();
    float r = red[0];
    __syncthreads();
    return r;
}

__device__ __forceinline__ float blkReduceSum(float v, float* red) {
#pragma unroll
    for (int o = 16; o; o >>= 1) v += __shfl_xor_sync(0xffffffffu, v, o);
    if ((threadIdx.x & 31) == 0) red[threadIdx.x >> 5] = v;
    __syncthreads();
    if (threadIdx.x == 0) {
        float m = red[0];
#pragma unroll
        for (int i = 1; i < 8; i++) m += red[i];
        red[0] = m;
    }
    __syncthreads();
    float r = red[0];
    __syncthreads();
    return r;
}

__global__ void attn_row_kernel() {
    const float* S = g_arena + OFF_SC;
    const float* v = g_arena + OFF_V;
    float* o = g_arena + OFF_O;

    __shared__ unsigned hist[256];
    __shared__ int sel_idx[NSEQ];      // worst-case tie blowup
    __shared__ float sel_p[NSEQ];
    __shared__ float red[8];
    __shared__ float part[256];
    __shared__ unsigned sh_pref, sh_k;

    int row = blockIdx.x;
    int n = row & (NSEQ - 1);
    int bh = row >> 11;
    int h = bh & (HH - 1), b = bh >> 3;
    int t = threadIdx.x;

    const float* srow = S + ((size_t)bh * NSEQ + n) * NSEQ;

    // Load 8 scores per thread into registers; keys + running max.
    float val8[8];
    unsigned key8[8];
    float m = -INFINITY;
#pragma unroll
    for (int r = 0; r < 8; r++) {
        float sv = srow[t + 256 * r];
        val8[r] = sv;
        key8[r] = fkey(sv);
        m = fmaxf(m, sv);
    }
    if (t == 0) { sh_pref = 0u; sh_k = KSP; }
    m = blkReduceMax(m, red);          // syncs also publish sh_pref/sh_k

    // Radix select: exact 32nd-largest key (counting duplicates, matching
    // jax.lax.top_k's k-th sorted value under the >= comparison).
#pragma unroll 1
    for (int shift = 24; shift >= 0; shift -= 8) {
        hist[t] = 0u;
        __syncthreads();
        unsigned pref = sh_pref;
        unsigned kneed = sh_k;
        unsigned mask = (shift == 24) ? 0u : (0xFFFFFFFFu << (shift + 8));
#pragma unroll
        for (int r = 0; r < 8; r++)
            if ((key8[r] & mask) == pref)
                atomicAdd(&hist[(key8[r] >> shift) & 255u], 1u);
        __syncthreads();
        // inclusive suffix sums over 256 buckets
        for (int off = 1; off < 256; off <<= 1) {
            unsigned add = (t + off < 256) ? hist[t + off] : 0u;
            __syncthreads();
            hist[t] += add;
            __syncthreads();
        }
        unsigned suf = hist[t];
        unsigned sufN = (t < 255) ? hist[t + 1] : 0u;
        if (suf >= kneed && sufN < kneed) {
            sh_pref = pref | ((unsigned)t << shift);
            sh_k = kneed - sufN;
        }
        __syncthreads();
    }
    unsigned thr = sh_pref;

    // Deterministic compaction of surviving entries (rank by thread order).
    unsigned pass8 = 0u;
    int cnt_t = 0;
#pragma unroll
    for (int r = 0; r < 8; r++)
        if (key8[r] >= thr) { pass8 |= (1u << r); cnt_t++; }
    hist[t] = (unsigned)cnt_t;
    __syncthreads();
    for (int off = 1; off < 256; off <<= 1) {      // inclusive prefix sums
        unsigned add = (t >= off) ? hist[t - off] : 0u;
        __syncthreads();
        hist[t] += add;
        __syncthreads();
    }
    int pos = (int)hist[t] - cnt_t;
    int cnt = (int)hist[255];
#pragma unroll
    for (int r = 0; r < 8; r++)
        if (pass8 & (1u << r)) {
            sel_idx[pos] = t + 256 * r;
            sel_p[pos] = val8[r];
            pos++;
        }
    __syncthreads();

    // Sparse exp + sum (only ~32 entries)
    float loc = 0.f;
    for (int e = t; e < cnt; e += 256) {
        float p = __expf(sel_p[e] - m);
        sel_p[e] = p;
        loc += p;
    }
    float tot = blkReduceSum(loc, red);            // syncs publish sel_p
    float inv = 1.f / tot;

    // Sparse P @ V: warp w handles entries e ≡ w (mod 8); lane d reads
    // V[sel_idx[e]][h*32+d] — one fully-coalesced 128B row per entry.
    int w = t >> 5, d = t & 31;
    const float* vb = v + ((size_t)b * NSEQ) * DMODEL + h * DHD + d;
    float acc = 0.f;
    for (int e = w; e < cnt; e += 8)
        acc += sel_p[e] * vb[(size_t)sel_idx[e] * DMODEL];
    part[t] = acc;
    __syncthreads();
    if (t < 32) {
        float r = part[t];
#pragma unroll
        for (int ww = 1; ww < 8; ww++) r += part[ww * 32 + t];
        o[((size_t)b * NSEQ + n) * DMODEL + h * DHD + t] = r * inv;
    }
}

// ---------------------------------------------------------------------------
// BatchNorm over (B,N) per channel — deterministic two-stage reduction.
// ---------------------------------------------------------------------------
__global__ void bn_partial_kernel() {
    const float* X = g_arena + OFF_H;
    float* ps = g_arena + OFF_PS;
    float* pq = g_arena + OFF_PQ;
    int blk = blockIdx.x;
    int t = threadIdx.x;
    float s = 0.f, q = 0.f;
    for (int r = 0; r < 128; r++) {
        float val = X[(size_t)(blk * 128 + r) * DMODEL + t];
        s += val;
        q += val * val;
    }
    ps[blk * DMODEL + t] = s;
    pq[blk * DMODEL + t] = q;
}

__global__ void bn_finalize_kernel() {
    const float* ps = g_arena + OFF_PS;
    const float* pq = g_arena + OFF_PQ;
    float* stat = g_arena + OFF_ST;
    int t = threadIdx.x;
    float s = 0.f, q = 0.f;
    for (int b = 0; b < 64; b++) {
        s += ps[b * DMODEL + t];
        q += pq[b * DMODEL + t];
    }
    float mu = s * (1.0f / (float)MROWS);
    float var = q * (1.0f / (float)MROWS) - mu * mu;
    stat[t] = mu;
    stat[DMODEL + t] = rsqrtf(var + 1e-5f);
}

__global__ void bn_apply_kernel(const float* __restrict__ gamma,
                                const float* __restrict__ beta,
                                float* __restrict__ out) {
    const float* X = g_arena + OFF_H;
    const float* stat = g_arena + OFF_ST;
    size_t idx = (size_t)blockIdx.x * 256 + threadIdx.x;
    int c = (int)(idx & (DMODEL - 1));
    out[idx] = (X[idx] - stat[c]) * stat[DMODEL + c] * gamma[c] + beta[c];
}

// ---------------------------------------------------------------------------
// Launch — kernel launches ONLY (graph-capture safe)
// ---------------------------------------------------------------------------
extern "C" void kernel_launch(void* const* d_in, const int* in_sizes, int n_in,
                              void* d_out, int out_size) {
    const float* x    = (const float*)d_in[0];
    const float* U_np = (const float*)d_in[1];
    const float* V_np = (const float*)d_in[2];
    const float* b_np = (const float*)d_in[3];
    const float* U_q  = (const float*)d_in[4];
    const float* V_q  = (const float*)d_in[5];
    const float* U_k  = (const float*)d_in[6];
    const float* V_k  = (const float*)d_in[7];
    const float* U_v  = (const float*)d_in[8];
    const float* V_v  = (const float*)d_in[9];
    const float* U_o  = (const float*)d_in[10];
    const float* V_o  = (const float*)d_in[11];
    const float* b_o  = (const float*)d_in[12];
    const float* U_op = (const float*)d_in[13];
    const float* V_op = (const float*)d_in[14];
    const float* b_op = (const float*)d_in[15];
    const float* gamma = (const float*)d_in[16];
    const float* beta  = (const float*)d_in[17];
    float* out = (float*)d_out;

    dim3 gN1(1, MROWS / 64);   // Nn = 64
    dim3 gN4(4, MROWS / 64);   // Nn = 256

    // h = (x @ U_np) @ V_np + b_np
    sgemm_kernel<<<gN1, 256>>>(x, 0, U_np, nullptr, OFF_T, MROWS, RR, DMODEL);
    sgemm_kernel<<<gN4, 256>>>(nullptr, OFF_T, V_np, b_np, OFF_H, MROWS, DMODEL, RR);
    // q, k, v
    sgemm_kernel<<<gN1, 256>>>(nullptr, OFF_H, U_q, nullptr, OFF_T, MROWS, RR, DMODEL);
    sgemm_kernel<<<gN4, 256>>>(nullptr, OFF_T, V_q, nullptr, OFF_Q, MROWS, DMODEL, RR);
    sgemm_kernel<<<gN1, 256>>>(nullptr, OFF_H, U_k, nullptr, OFF_T, MROWS, RR, DMODEL);
    sgemm_kernel<<<gN4, 256>>>(nullptr, OFF_T, V_k, nullptr, OFF_K, MROWS, DMODEL, RR);
    sgemm_kernel<<<gN1, 256>>>(nullptr, OFF_H, U_v, nullptr, OFF_T, MROWS, RR, DMODEL);
    sgemm_kernel<<<gN4, 256>>>(nullptr, OFF_T, V_v, nullptr, OFF_V, MROWS, DMODEL, RR);

    // scores
    qk_kernel<<<dim3(NSEQ / 64, NSEQ / 64, BSZ * HH), 256>>>();
    // top-k + softmax + sparse PV
    attn_row_kernel<<<BSZ * HH * NSEQ, 256>>>();

    // attention out proj + out_proj
    sgemm_kernel<<<gN1, 256>>>(nullptr, OFF_O, U_o, nullptr, OFF_T, MROWS, RR, DMODEL);
    sgemm_kernel<<<gN4, 256>>>(nullptr, OFF_T, V_o, b_o, OFF_O2, MROWS, DMODEL, RR);
    sgemm_kernel<<<gN1, 256>>>(nullptr, OFF_O2, U_op, nullptr, OFF_T, MROWS, RR, DMODEL);
    sgemm_kernel<<<gN4, 256>>>(nullptr, OFF_T, V_op, b_op, OFF_H, MROWS, DMODEL, RR);

    // BatchNorm
    bn_partial_kernel<<<64, 256>>>();
    bn_finalize_kernel<<<1, 256>>>();
    bn_apply_kernel<<<(MROWS * DMODEL) / 256, 256>>>(gamma, beta, out);
}

// round 4
// speedup vs baseline: 2.3668x; 1.0979x over previous
#include <cuda_runtime.h>
#include <math.h>
#include <stdint.h>

// Problem constants
#define BSZ 4
#define NSEQ 2048
#define DMODEL 256
#define HH 8
#define DHD 32
#define RR 64
#define KSP 32
#define MROWS (BSZ * NSEQ)   // 8192

// ---------------------------------------------------------------------------
// Scratch arena (float offsets), compile-time indexed.
// OFF_T holds 3 slices (t_q,t_k,t_v) for the batched QKV stage-2.
// OFF_Q/OFF_K/OFF_V are contiguous so batched stage-2 writes via z*stride.
// ---------------------------------------------------------------------------
#define OFF_T   ((size_t)0)                                   // 3 * 8192*64
#define OFF_H   (OFF_T  + (size_t)3 * MROWS * RR)
#define OFF_Q   (OFF_H  + (size_t)MROWS * DMODEL)
#define OFF_K   (OFF_Q  + (size_t)MROWS * DMODEL)
#define OFF_V   (OFF_K  + (size_t)MROWS * DMODEL)
#define OFF_O   (OFF_V  + (size_t)MROWS * DMODEL)
#define OFF_O2  (OFF_O  + (size_t)MROWS * DMODEL)
#define OFF_SC  (OFF_O2 + (size_t)MROWS * DMODEL)             // 512 MB scores
#define OFF_PS  (OFF_SC + (size_t)BSZ * HH * NSEQ * NSEQ)
#define OFF_PQ  (OFF_PS + (size_t)64 * DMODEL)
#define OFF_ST  (OFF_PQ + (size_t)64 * DMODEL)
#define ARENA_TOTAL (OFF_ST + (size_t)2 * DMODEL)

__device__ float g_arena[ARENA_TOTAL];

// ---------------------------------------------------------------------------
// Shared GEMM body: C[M,N] = A[M,K] @ B[K,N] (+ bias[N])
// BM=BN=64, BK=16, 256 threads, 4x4 per thread.
// ---------------------------------------------------------------------------
__device__ __forceinline__ void gemm_body(const float* __restrict__ A,
                                          const float* __restrict__ Bm,
                                          const float* __restrict__ bias,
                                          float* __restrict__ C,
                                          int Nn, int K) {
    __shared__ float As[16][65];   // [k][m]
    __shared__ float Bs[16][65];   // [k][n]
    int tid = threadIdx.x;
    int tx = tid & 15, ty = tid >> 4;
    int m0 = blockIdx.y * 64, n0 = blockIdx.x * 64;
    float acc[4][4] = {};

    for (int k0 = 0; k0 < K; k0 += 16) {
#pragma unroll
        for (int r = 0; r < 4; r++) {
            int idx = tid + r * 256;
            int m = idx >> 4;
            int kk = idx & 15;
            As[kk][m] = A[(size_t)(m0 + m) * K + k0 + kk];
        }
#pragma unroll
        for (int r = 0; r < 4; r++) {
            int idx = tid + r * 256;
            int kk = idx >> 6;
            int nn = idx & 63;
            Bs[kk][nn] = Bm[(size_t)(k0 + kk) * Nn + n0 + nn];
        }
        __syncthreads();
#pragma unroll
        for (int kk = 0; kk < 16; kk++) {
            float a4[4], b4[4];
#pragma unroll
            for (int i = 0; i < 4; i++) a4[i] = As[kk][ty * 4 + i];
#pragma unroll
            for (int j = 0; j < 4; j++) b4[j] = Bs[kk][tx * 4 + j];
#pragma unroll
            for (int i = 0; i < 4; i++)
#pragma unroll
                for (int j = 0; j < 4; j++)
                    acc[i][j] += a4[i] * b4[j];
        }
        __syncthreads();
    }
#pragma unroll
    for (int i = 0; i < 4; i++) {
        int m = m0 + ty * 4 + i;
#pragma unroll
        for (int j = 0; j < 4; j++) {
            int n = n0 + tx * 4 + j;
            float v = acc[i][j];
            if (bias) v += bias[n];
            C[(size_t)m * Nn + n] = v;
        }
    }
}

__global__ void sgemm_kernel(const float* __restrict__ Aext, size_t aOff,
                             const float* __restrict__ Bm,
                             const float* __restrict__ bias,
                             size_t cOff, int Nn, int K) {
    const float* A = Aext ? Aext : (g_arena + aOff);
    gemm_body(A, Bm, bias, g_arena + cOff, Nn, K);
}

// Batched over blockIdx.z = 0,1,2 (Q,K,V): A at aOff + z*aStride, C at
// cOff + z*cStride, B selected from {B0,B1,B2}.
__global__ void sgemm3_kernel(size_t aOff, size_t aStride,
                              const float* __restrict__ B0,
                              const float* __restrict__ B1,
                              const float* __restrict__ B2,
                              size_t cOff, size_t cStride, int Nn, int K) {
    int z = blockIdx.z;
    const float* Bm = (z == 0) ? B0 : (z == 1) ? B1 : B2;
    gemm_body(g_arena + aOff + (size_t)z * aStride, Bm, nullptr,
              g_arena + cOff + (size_t)z * cStride, Nn, K);
}

// ---------------------------------------------------------------------------
// QK^T scores per (b,h): S[bh][i][j] = (q_i . k_j) / sqrt(32)
// ---------------------------------------------------------------------------
__global__ void qk_kernel() {
    const float* q = g_arena + OFF_Q;
    const float* k = g_arena + OFF_K;
    float* S = g_arena + OFF_SC;
    int bh = blockIdx.z;
    int h = bh & (HH - 1), b = bh >> 3;
    int i0 = blockIdx.y * 64, j0 = blockIdx.x * 64;
    __shared__ float Qs[64][33];
    __shared__ float Ks[64][33];
    int tid = threadIdx.x;
    int d = tid & 31, r0 = tid >> 5;
    const float* qb = q + ((size_t)b * NSEQ) * DMODEL + h * DHD;
    const float* kb = k + ((size_t)b * NSEQ) * DMODEL + h * DHD;
#pragma unroll
    for (int r = r0; r < 64; r += 8) {
        Qs[r][d] = qb[(size_t)(i0 + r) * DMODEL + d];
        Ks[r][d] = kb[(size_t)(j0 + r) * DMODEL + d];
    }
    __syncthreads();
    int tx = tid & 15, ty = tid >> 4;
    float acc[4][4] = {};
#pragma unroll
    for (int dd = 0; dd < 32; dd++) {
        float a4[4], b4[4];
#pragma unroll
        for (int i = 0; i < 4; i++) a4[i] = Qs[ty * 4 + i][dd];
#pragma unroll
        for (int j = 0; j < 4; j++) b4[j] = Ks[tx * 4 + j][dd];
#pragma unroll
        for (int i = 0; i < 4; i++)
#pragma unroll
            for (int j = 0; j < 4; j++)
                acc[i][j] += a4[i] * b4[j];
    }
    const float scale = 1.0f / sqrtf(32.0f);
    float* Sp = S + ((size_t)bh * NSEQ + i0) * NSEQ + j0;
#pragma unroll
    for (int i = 0; i < 4; i++) {
        float4 v4 = make_float4(acc[i][0] * scale, acc[i][1] * scale,
                                acc[i][2] * scale, acc[i][3] * scale);
        *reinterpret_cast<float4*>(Sp + (size_t)(ty * 4 + i) * NSEQ + tx * 4) = v4;
    }
}

// ---------------------------------------------------------------------------
// Fused per-row: exact top-32 (radix select with warp-shuffle scans),
// deterministic compaction, sparse exp + sparse P @ V.
// ---------------------------------------------------------------------------
__device__ __forceinline__ unsigned fkey(float f) {
    unsigned u = __float_as_uint(f);
    return u ^ (((int)u < 0) ? 0xFFFFFFFFu : 0x80000000u);
}

__device__ __forceinline__ float blkReduceMax(float v, float* red) {
#pragma unroll
    for (int o = 16; o; o >>= 1) v = fmaxf(v, __shfl_xor_sync(0xffffffffu, v, o));
    if ((threadIdx.x & 31) == 0) red[threadIdx.x >> 5] = v;
    __syncthreads();
    float m = red[0];
#pragma unroll
    for (int i = 1; i < 8; i++) m = fmaxf(m, red[i]);
    return m;   // every thread computes the same value; no extra sync
}

__device__ __forceinline__ float blkReduceSum(float v, float* red) {
#pragma unroll
    for (int o = 16; o; o >>= 1) v += __shfl_xor_sync(0xffffffffu, v, o);
    if ((threadIdx.x & 31) == 0) red[threadIdx.x >> 5] = v;
    __syncthreads();
    float m = red[0];
#pragma unroll
    for (int i = 1; i < 8; i++) m += red[i];
    return m;
}

__global__ void attn_row_kernel() {
    const float* S = g_arena + OFF_SC;
    const float* v = g_arena + OFF_V;
    float* o = g_arena + OFF_O;

    __shared__ unsigned hist[256];
    __shared__ unsigned wsum[8];
    __shared__ int sel_idx[NSEQ];
    __shared__ float sel_p[NSEQ];
    __shared__ float red[8];
    __shared__ float part[256];
    __shared__ unsigned sh_pref, sh_k;

    int row = blockIdx.x;
    int n = row & (NSEQ - 1);
    int bh = row >> 11;
    int h = bh & (HH - 1), b = bh >> 3;
    int t = threadIdx.x;
    int lane = t & 31, w = t >> 5;

    const float4* srow4 = reinterpret_cast<const float4*>(
        S + ((size_t)bh * NSEQ + n) * NSEQ);

    // Thread t owns indices 8t..8t+7 (two streaming float4 loads).
    float val8[8];
    unsigned key8[8];
    float4 va = __ldcs(srow4 + 2 * t);
    float4 vb = __ldcs(srow4 + 2 * t + 1);
    val8[0] = va.x; val8[1] = va.y; val8[2] = va.z; val8[3] = va.w;
    val8[4] = vb.x; val8[5] = vb.y; val8[6] = vb.z; val8[7] = vb.w;
    float m = -INFINITY;
#pragma unroll
    for (int r = 0; r < 8; r++) {
        key8[r] = fkey(val8[r]);
        m = fmaxf(m, val8[r]);
    }
    if (t == 0) { sh_pref = 0u; sh_k = KSP; }
    m = blkReduceMax(m, red);   // its sync publishes sh_pref/sh_k

    // Radix select: exact 32nd-largest key (duplicates counted — matches
    // jax.lax.top_k's k-th sorted value under >= threshold semantics).
#pragma unroll 1
    for (int shift = 24; shift >= 0; shift -= 8) {
        hist[t] = 0u;
        unsigned pref = sh_pref;
        unsigned kneed = sh_k;
        __syncthreads();
        unsigned mask = (shift == 24) ? 0u : (0xFFFFFFFFu << (shift + 8));
#pragma unroll
        for (int r = 0; r < 8; r++)
            if ((key8[r] & mask) == pref)
                atomicAdd(&hist[(key8[r] >> shift) & 255u], 1u);
        __syncthreads();
        unsigned own = hist[t];
        // warp-level inclusive suffix scan of 256 buckets
        unsigned sv = own;
#pragma unroll
        for (int off = 1; off < 32; off <<= 1) {
            unsigned u = __shfl_down_sync(0xffffffffu, sv, off);
            if (lane + off < 32) sv += u;
        }
        if (lane == 0) wsum[w] = sv;   // lane0 holds this warp's total
        __syncthreads();
        unsigned add = 0u;
#pragma unroll
        for (int w2 = 0; w2 < 8; w2++)
            if (w2 > w) add += wsum[w2];
        unsigned suf = sv + add;              // inclusive suffix sum at t
        if (suf >= kneed && (suf - own) < kneed) {
            sh_pref = pref | ((unsigned)t << shift);
            sh_k = kneed - (suf - own);
        }
        __syncthreads();
    }
    unsigned thr = sh_pref;

    // Deterministic compaction (rank by global index order within thread).
    unsigned pass8 = 0u;
    unsigned cnt_t = 0u;
#pragma unroll
    for (int r = 0; r < 8; r++)
        if (key8[r] >= thr) { pass8 |= (1u << r); cnt_t++; }
    // warp-level inclusive prefix scan of per-thread counts
    unsigned pv = cnt_t;
#pragma unroll
    for (int off = 1; off < 32; off <<= 1) {
        unsigned u = __shfl_up_sync(0xffffffffu, pv, off);
        if (lane >= off) pv += u;
    }
    if (lane == 31) wsum[w] = pv;
    __syncthreads();
    unsigned addp = 0u;
    unsigned cnt_all = 0u;
#pragma unroll
    for (int w2 = 0; w2 < 8; w2++) {
        unsigned ws = wsum[w2];
        if (w2 < w) addp += ws;
        cnt_all += ws;
    }
    int pos = (int)(pv + addp - cnt_t);
    int cnt = (int)cnt_all;
#pragma unroll
    for (int r = 0; r < 8; r++)
        if (pass8 & (1u << r)) {
            sel_idx[pos] = 8 * t + r;
            sel_p[pos] = val8[r];
            pos++;
        }
    __syncthreads();

    // Sparse exp + sum (~32 entries)
    float loc = 0.f;
    for (int e = t; e < cnt; e += 256) {
        float p = __expf(sel_p[e] - m);
        sel_p[e] = p;
        loc += p;
    }
    float tot = blkReduceSum(loc, red);   // sync publishes sel_p
    float inv = 1.f / tot;

    // Sparse P @ V: warp w handles entries e ≡ w (mod 8); lane d gathers
    // V[sel_idx[e]][h*32+d] — one coalesced 128B row per entry.
    int d = lane;
    const float* vbp = v + ((size_t)b * NSEQ) * DMODEL + h * DHD + d;
    float acc = 0.f;
    for (int e = w; e < cnt; e += 8)
        acc += sel_p[e] * vbp[(size_t)sel_idx[e] * DMODEL];
    part[t] = acc;
    __syncthreads();
    if (t < 32) {
        float r = part[t];
#pragma unroll
        for (int ww = 1; ww < 8; ww++) r += part[ww * 32 + t];
        o[((size_t)b * NSEQ + n) * DMODEL + h * DHD + t] = r * inv;
    }
}

// ---------------------------------------------------------------------------
// BatchNorm over (B,N) per channel — deterministic two-stage reduction.
// ---------------------------------------------------------------------------
__global__ void bn_partial_kernel() {
    const float* X = g_arena + OFF_H;
    float* ps = g_arena + OFF_PS;
    float* pq = g_arena + OFF_PQ;
    int blk = blockIdx.x;
    int t = threadIdx.x;
    float s = 0.f, q = 0.f;
    for (int r = 0; r < 128; r++) {
        float val = X[(size_t)(blk * 128 + r) * DMODEL + t];
        s += val;
        q += val * val;
    }
    ps[blk * DMODEL + t] = s;
    pq[blk * DMODEL + t] = q;
}

__global__ void bn_finalize_kernel() {
    const float* ps = g_arena + OFF_PS;
    const float* pq = g_arena + OFF_PQ;
    float* stat = g_arena + OFF_ST;
    int t = threadIdx.x;
    float s = 0.f, q = 0.f;
    for (int b = 0; b < 64; b++) {
        s += ps[b * DMODEL + t];
        q += pq[b * DMODEL + t];
    }
    float mu = s * (1.0f / (float)MROWS);
    float var = q * (1.0f / (float)MROWS) - mu * mu;
    stat[t] = mu;
    stat[DMODEL + t] = rsqrtf(var + 1e-5f);
}

__global__ void bn_apply_kernel(const float* __restrict__ gamma,
                                const float* __restrict__ beta,
                                float* __restrict__ out) {
    const float* X = g_arena + OFF_H;
    const float* stat = g_arena + OFF_ST;
    size_t idx = (size_t)blockIdx.x * 256 + threadIdx.x;
    int c = (int)(idx & (DMODEL - 1));
    out[idx] = (X[idx] - stat[c]) * stat[DMODEL + c] * gamma[c] + beta[c];
}

// ---------------------------------------------------------------------------
// Launch — kernel launches ONLY (graph-capture safe)
// ---------------------------------------------------------------------------
extern "C" void kernel_launch(void* const* d_in, const int* in_sizes, int n_in,
                              void* d_out, int out_size) {
    const float* x    = (const float*)d_in[0];
    const float* U_np = (const float*)d_in[1];
    const float* V_np = (const float*)d_in[2];
    const float* b_np = (const float*)d_in[3];
    const float* U_q  = (const float*)d_in[4];
    const float* V_q  = (const float*)d_in[5];
    const float* U_k  = (const float*)d_in[6];
    const float* V_k  = (const float*)d_in[7];
    const float* U_v  = (const float*)d_in[8];
    const float* V_v  = (const float*)d_in[9];
    const float* U_o  = (const float*)d_in[10];
    const float* V_o  = (const float*)d_in[11];
    const float* b_o  = (const float*)d_in[12];
    const float* U_op = (const float*)d_in[13];
    const float* V_op = (const float*)d_in[14];
    const float* b_op = (const float*)d_in[15];
    const float* gamma = (const float*)d_in[16];
    const float* beta  = (const float*)d_in[17];
    float* out = (float*)d_out;

    dim3 gN1(1, MROWS / 64);        // Nn = 64
    dim3 gN4(4, MROWS / 64);        // Nn = 256
    dim3 gN1z(1, MROWS / 64, 3);    // batched QKV stage-1
    dim3 gN4z(4, MROWS / 64, 3);    // batched QKV stage-2

    // h = (x @ U_np) @ V_np + b_np
    sgemm_kernel<<<gN1, 256>>>(x, 0, U_np, nullptr, OFF_T, RR, DMODEL);
    sgemm_kernel<<<gN4, 256>>>(nullptr, OFF_T, V_np, b_np, OFF_H, DMODEL, RR);
    // q,k,v: batched stage-1 (shared A = h) then batched stage-2
    sgemm3_kernel<<<gN1z, 256>>>(OFF_H, 0, U_q, U_k, U_v,
                                 OFF_T, (size_t)MROWS * RR, RR, DMODEL);
    sgemm3_kernel<<<gN4z, 256>>>(OFF_T, (size_t)MROWS * RR, V_q, V_k, V_v,
                                 OFF_Q, (size_t)MROWS * DMODEL, DMODEL, RR);

    // scores
    qk_kernel<<<dim3(NSEQ / 64, NSEQ / 64, BSZ * HH), 256>>>();
    // top-k + softmax + sparse PV
    attn_row_kernel<<<BSZ * HH * NSEQ, 256>>>();

    // attention out proj + out_proj
    sgemm_kernel<<<gN1, 256>>>(nullptr, OFF_O, U_o, nullptr, OFF_T, RR, DMODEL);
    sgemm_kernel<<<gN4, 256>>>(nullptr, OFF_T, V_o, b_o, OFF_O2, DMODEL, RR);
    sgemm_kernel<<<gN1, 256>>>(nullptr, OFF_O2, U_op, nullptr, OFF_T, RR, DMODEL);
    sgemm_kernel<<<gN4, 256>>>(nullptr, OFF_T, V_op, b_op, OFF_H, DMODEL, RR);

    // BatchNorm
    bn_partial_kernel<<<64, 256>>>();
    bn_finalize_kernel<<<1, 256>>>();
    bn_apply_kernel<<<(MROWS * DMODEL) / 256, 256>>>(gamma, beta, out);
}